// round 3
// baseline (speedup 1.0000x reference)
#include <cuda_runtime.h>

#define Nn   1000
#define NP   1024      // padded
#define Bb   8

// Scratch (static __device__ — no allocation). Padded to NP.
__device__ float4 g_EA[NP];
__device__ float4 g_EB[NP];       // pad rows = (0,0,0,1) -> d contribution 1, w = 0
__device__ float4 g_xt[2 * NP];   // xt[i] = x[0..7][i] transposed; pad rows = 0
__device__ float  g_cc[32];       // c0/c1/c2 [k][m] (18) + Wf2v (3) + bf2v (1)

// ---------------------------------------------------------------------------
// Kernel 1: single block, 1024 threads, single pass. Thread t owns row i=t.
// ---------------------------------------------------------------------------
__global__ void __launch_bounds__(1024) k_pre(
    const float* __restrict__ x,
    const float* __restrict__ W1,   const float* __restrict__ b1,
    const float* __restrict__ W2,   const float* __restrict__ b2,
    const float* __restrict__ Wf1e, const float* __restrict__ bf1e,
    const float* __restrict__ Wf2e, const float* __restrict__ bf2e,
    const float* __restrict__ Wfk,  const float* __restrict__ bfk,
    const float* __restrict__ Wf1v, const float* __restrict__ bf1v,
    const float* __restrict__ Wf2v, const float* __restrict__ bf2v)
{
    __shared__ float s_red[32];
    const int tid = threadIdx.x;
    const bool live = (tid < Nn);

    // --- load & transpose my row; sx in register ---
    float v[8];
    float sxi = 0.f;
    #pragma unroll
    for (int b = 0; b < 8; b++) {
        v[b] = live ? x[b * Nn + tid] : 0.f;
        sxi += v[b];
    }
    g_xt[2 * tid]     = make_float4(v[0], v[1], v[2], v[3]);
    g_xt[2 * tid + 1] = make_float4(v[4], v[5], v[6], v[7]);

    // --- global sum X ---
    float px = sxi;
    #pragma unroll
    for (int off = 16; off > 0; off >>= 1)
        px += __shfl_xor_sync(0xffffffffu, px, off);
    if ((tid & 31) == 0) s_red[tid >> 5] = px;
    __syncthreads();
    if (tid < 32) {
        float t = s_red[tid];
        #pragma unroll
        for (int off = 16; off > 0; off >>= 1)
            t += __shfl_xor_sync(0xffffffffu, t, off);
        if (tid == 0) s_red[0] = t;
    }
    __syncthreads();
    const float X = s_red[0];

    // --- scalar coefficients (redundant per thread) ---
    float alpha[2], beta[2], gamma[2];
    #pragma unroll
    for (int f = 0; f < 2; f++) {
        float sa = 0.f, sb = 0.f, sg = 0.f;
        #pragma unroll
        for (int e = 0; e < 4; e++) {
            float we = Wf1e[(2 * e) * 2 + f];
            float wo = Wf1e[(2 * e + 1) * 2 + f];
            sa += W1[e] * we;
            sb += W1[e] * wo;
            sg += b1[e] * (we + wo);
        }
        alpha[f] = (float)Nn * sa;
        beta[f]  = sb;
        gamma[f] = (float)Nn * (sg + bf1e[f]);
    }
    float ap[3], cv[3];
    #pragma unroll
    for (int vv = 0; vv < 3; vv++) {
        float a = 0.f, bq = 0.f, g = 0.f;
        #pragma unroll
        for (int f = 0; f < 2; f++) {
            float w = Wf1v[f * 3 + vv];
            a  += alpha[f] * w;
            bq += beta[f]  * w;
            g  += gamma[f] * w;
        }
        g += bf1v[vv];
        ap[vv] = a;
        cv[vv] = bq * X + (float)Bb * g;
    }
    float aA[3], cA[3], aB[3], cB[3];
    #pragma unroll
    for (int k = 0; k < 3; k++) {
        float s1 = 0.f, s2 = 0.f, s3 = 0.f, s4 = 0.f;
        #pragma unroll
        for (int vv = 0; vv < 3; vv++) {
            float we = Wf2e[(2 * vv) * 3 + k];
            float wo = Wf2e[(2 * vv + 1) * 3 + k];
            s1 += ap[vv] * we;  s2 += cv[vv] * we;
            s3 += ap[vv] * wo;  s4 += cv[vv] * wo;
        }
        aA[k] = s1; cA[k] = s2 + bf2e[k];
        aB[k] = s3; cB[k] = s4;
    }

    // --- EA/EB (per-side max-subtracted; exact for factorized softmax) ---
    if (live) {
        float A0 = fmaf(aA[0], sxi, cA[0]);
        float A1 = fmaf(aA[1], sxi, cA[1]);
        float A2 = fmaf(aA[2], sxi, cA[2]);
        float mA = fmaxf(A0, fmaxf(A1, A2));
        g_EA[tid] = make_float4(__expf(A0 - mA), __expf(A1 - mA), __expf(A2 - mA), 0.f);
        float B0 = fmaf(aB[0], sxi, cB[0]);
        float B1 = fmaf(aB[1], sxi, cB[1]);
        float B2 = fmaf(aB[2], sxi, cB[2]);
        float mB = fmaxf(B0, fmaxf(B1, B2));
        g_EB[tid] = make_float4(__expf(B0 - mB), __expf(B1 - mB), __expf(B2 - mB), 0.f);
    } else {
        g_EA[tid] = make_float4(0.f, 0.f, 0.f, 0.f);
        g_EB[tid] = make_float4(0.f, 0.f, 0.f, 1.f);  // pad: d += 1, w = 0
    }

    // --- message-combine constants ---
    if (tid == 0) {
        #pragma unroll
        for (int k = 0; k < 3; k++)
            #pragma unroll
            for (int m = 0; m < 2; m++) {
                float u1 = 0.f, v1 = 0.f, u2 = 0.f, v2 = 0.f;
                #pragma unroll
                for (int e = 0; e < 4; e++) {
                    float we = Wfk[k * 16 + (2 * e) * 2 + m];
                    float wo = Wfk[k * 16 + (2 * e + 1) * 2 + m];
                    u1 += W2[e] * we;  v1 += b2[e] * we;
                    u2 += W2[e] * wo;  v2 += b2[e] * wo;
                }
                int km = k * 2 + m;
                g_cc[km * 3 + 0] = v1 + v2 + bfk[km];  // c0
                g_cc[km * 3 + 1] = u1;                 // c1
                g_cc[km * 3 + 2] = u2;                 // c2
            }
        g_cc[18] = Wf2v[0]; g_cc[19] = Wf2v[1];
        g_cc[20] = Wf2v[2]; g_cc[21] = bf2v[0];
    }
}

// ---------------------------------------------------------------------------
// Kernel 2: ONE WARP PER ROW i. 32 lanes stride over 1024 j's (32 iters each).
// No shared memory, no __syncthreads; single butterfly reduce per warp, then
// lanes 0..7 write the 8 batch outputs for row i.
// Grid: 250 blocks x 128 threads = 1000 warps.
// ---------------------------------------------------------------------------
__global__ void __launch_bounds__(128) k_main(float* __restrict__ out)
{
    const int lane = threadIdx.x & 31;
    const int i    = blockIdx.x * 4 + (threadIdx.x >> 5);
    const float4 ea = g_EA[i];

    float acc[27];
    #pragma unroll
    for (int v = 0; v < 27; v++) acc[v] = 0.f;

    #pragma unroll 4
    for (int u = 0; u < 32; u++) {
        const int j = u * 32 + lane;
        float4 eb = g_EB[j];
        float4 xa = g_xt[2 * j];
        float4 xb = g_xt[2 * j + 1];
        // pad rows: eb=(0,0,0,1) -> d=1, w=0, x=0 -> zero contribution
        float d = fmaf(ea.x, eb.x, fmaf(ea.y, eb.y, fmaf(ea.z, eb.z, eb.w)));
        float r = __fdividef(1.f, d);
        float w0 = eb.x * r, w1 = eb.y * r, w2 = eb.z * r;
        acc[0] += w0; acc[1] += w1; acc[2] += w2;
        float xv[8] = {xa.x, xa.y, xa.z, xa.w, xb.x, xb.y, xb.z, xb.w};
        float w[3]  = {w0, w1, w2};
        #pragma unroll
        for (int b = 0; b < 8; b++)
            #pragma unroll
            for (int k = 0; k < 3; k++)
                acc[3 + b * 3 + k] = fmaf(w[k], xv[b], acc[3 + b * 3 + k]);
    }

    // single warp butterfly reduce (deterministic); every lane gets totals
    #pragma unroll
    for (int v = 0; v < 27; v++) {
        #pragma unroll
        for (int off = 16; off > 0; off >>= 1)
            acc[v] += __shfl_xor_sync(0xffffffffu, acc[v], off);
    }

    if (lane < 8) {
        const int b = lane;
        float eav[3] = {ea.x, ea.y, ea.z};
        float xbi = ((const float*)&g_xt[2 * i])[b];
        float ve0 = 0.f, ve1 = 0.f;
        #pragma unroll
        for (int k = 0; k < 3; k++) {
            float Tk = eav[k] * acc[k];
            float Uk = eav[k] * acc[3 + b * 3 + k];
            ve0 += fmaf(xbi, g_cc[(k * 2 + 0) * 3 + 1], g_cc[(k * 2 + 0) * 3 + 0]) * Tk
                 + g_cc[(k * 2 + 0) * 3 + 2] * Uk;
            ve1 += fmaf(xbi, g_cc[(k * 2 + 1) * 3 + 1], g_cc[(k * 2 + 1) * 3 + 0]) * Tk
                 + g_cc[(k * 2 + 1) * 3 + 2] * Uk;
        }
        out[b * Nn + i] = xbi * (1.f + g_cc[20]) + g_cc[21]
                        + ve0 * g_cc[18] + ve1 * g_cc[19];
    }
}

extern "C" void kernel_launch(void* const* d_in, const int* in_sizes, int n_in,
                              void* d_out, int out_size)
{
    (void)in_sizes; (void)n_in; (void)out_size;
    k_pre<<<1, 1024>>>(
        (const float*)d_in[0],
        (const float*)d_in[1],  (const float*)d_in[2],
        (const float*)d_in[3],  (const float*)d_in[4],
        (const float*)d_in[5],  (const float*)d_in[6],
        (const float*)d_in[7],  (const float*)d_in[8],
        (const float*)d_in[9],  (const float*)d_in[10],
        (const float*)d_in[11], (const float*)d_in[12],
        (const float*)d_in[13], (const float*)d_in[14]);
    k_main<<<250, 128>>>((float*)d_out);
}

// round 4
// speedup vs baseline: 1.2596x; 1.2596x over previous
#include <cuda_runtime.h>

#define Nn   1000
#define NP   1024      // padded
#define Bb   8

// Scratch (static __device__ — no allocation). Padded to NP.
__device__ float4 g_EA[NP];
__device__ float4 g_EB[NP];       // pad rows = (0,0,0,1) -> d contribution 1, w = 0
__device__ float4 g_xt[2 * NP];   // xt[i] = x[0..7][i] transposed; pad rows = 0
__device__ float  g_cc[32];       // c0/c1/c2 [k][m] (18) + Wf2v (3) + bf2v (1)

// ---- packed f32x2 helpers (Blackwell) ----
__device__ __forceinline__ void ffma2(float2& d, const float2 a, const float2 b) {
    asm("fma.rn.f32x2 %0, %1, %2, %0;"
        : "+l"(reinterpret_cast<unsigned long long&>(d))
        : "l"(reinterpret_cast<const unsigned long long&>(a)),
          "l"(reinterpret_cast<const unsigned long long&>(b)));
}

// ---------------------------------------------------------------------------
// Kernel 1: single block, 1024 threads. Thread t owns row i=t. Coefficients
// computed on warp 0 only and broadcast via smem.
// ---------------------------------------------------------------------------
__global__ void __launch_bounds__(1024) k_pre(
    const float* __restrict__ x,
    const float* __restrict__ W1,   const float* __restrict__ b1,
    const float* __restrict__ W2,   const float* __restrict__ b2,
    const float* __restrict__ Wf1e, const float* __restrict__ bf1e,
    const float* __restrict__ Wf2e, const float* __restrict__ bf2e,
    const float* __restrict__ Wfk,  const float* __restrict__ bfk,
    const float* __restrict__ Wf1v, const float* __restrict__ bf1v,
    const float* __restrict__ Wf2v, const float* __restrict__ bf2v)
{
    __shared__ float s_red[32];
    __shared__ float s_coef[12];   // aA[3], cA[3], aB[3], cB[3]
    const int tid = threadIdx.x;
    const bool live = (tid < Nn);

    // --- load & transpose my row; sx in register ---
    float v[8];
    float sxi = 0.f;
    #pragma unroll
    for (int b = 0; b < 8; b++) {
        v[b] = live ? x[b * Nn + tid] : 0.f;
        sxi += v[b];
    }
    g_xt[2 * tid]     = make_float4(v[0], v[1], v[2], v[3]);
    g_xt[2 * tid + 1] = make_float4(v[4], v[5], v[6], v[7]);

    // --- global sum X ---
    float px = sxi;
    #pragma unroll
    for (int off = 16; off > 0; off >>= 1)
        px += __shfl_xor_sync(0xffffffffu, px, off);
    if ((tid & 31) == 0) s_red[tid >> 5] = px;
    __syncthreads();

    if (tid < 32) {
        float t = s_red[tid];
        #pragma unroll
        for (int off = 16; off > 0; off >>= 1)
            t += __shfl_xor_sync(0xffffffffu, t, off);
        const float X = t;

        // --- scalar coefficients (warp 0 only, redundant across 32 lanes) ---
        float alpha[2], beta[2], gamma[2];
        #pragma unroll
        for (int f = 0; f < 2; f++) {
            float sa = 0.f, sb = 0.f, sg = 0.f;
            #pragma unroll
            for (int e = 0; e < 4; e++) {
                float we = Wf1e[(2 * e) * 2 + f];
                float wo = Wf1e[(2 * e + 1) * 2 + f];
                sa += W1[e] * we;
                sb += W1[e] * wo;
                sg += b1[e] * (we + wo);
            }
            alpha[f] = (float)Nn * sa;
            beta[f]  = sb;
            gamma[f] = (float)Nn * (sg + bf1e[f]);
        }
        float ap[3], cv[3];
        #pragma unroll
        for (int vv = 0; vv < 3; vv++) {
            float a = 0.f, bq = 0.f, g = 0.f;
            #pragma unroll
            for (int f = 0; f < 2; f++) {
                float w = Wf1v[f * 3 + vv];
                a  += alpha[f] * w;
                bq += beta[f]  * w;
                g  += gamma[f] * w;
            }
            g += bf1v[vv];
            ap[vv] = a;
            cv[vv] = bq * X + (float)Bb * g;
        }
        #pragma unroll
        for (int k = 0; k < 3; k++) {
            float s1 = 0.f, s2 = 0.f, s3 = 0.f, s4 = 0.f;
            #pragma unroll
            for (int vv = 0; vv < 3; vv++) {
                float we = Wf2e[(2 * vv) * 3 + k];
                float wo = Wf2e[(2 * vv + 1) * 3 + k];
                s1 += ap[vv] * we;  s2 += cv[vv] * we;
                s3 += ap[vv] * wo;  s4 += cv[vv] * wo;
            }
            if (tid == 0) {
                s_coef[k]     = s1;            // aA
                s_coef[3 + k] = s2 + bf2e[k];  // cA
                s_coef[6 + k] = s3;            // aB
                s_coef[9 + k] = s4;            // cB
            }
        }

        // --- message-combine constants (lane 0) ---
        if (tid == 0) {
            #pragma unroll
            for (int k = 0; k < 3; k++)
                #pragma unroll
                for (int m = 0; m < 2; m++) {
                    float u1 = 0.f, v1 = 0.f, u2 = 0.f, v2 = 0.f;
                    #pragma unroll
                    for (int e = 0; e < 4; e++) {
                        float we = Wfk[k * 16 + (2 * e) * 2 + m];
                        float wo = Wfk[k * 16 + (2 * e + 1) * 2 + m];
                        u1 += W2[e] * we;  v1 += b2[e] * we;
                        u2 += W2[e] * wo;  v2 += b2[e] * wo;
                    }
                    int km = k * 2 + m;
                    g_cc[km * 3 + 0] = v1 + v2 + bfk[km];
                    g_cc[km * 3 + 1] = u1;
                    g_cc[km * 3 + 2] = u2;
                }
            g_cc[18] = Wf2v[0]; g_cc[19] = Wf2v[1];
            g_cc[20] = Wf2v[2]; g_cc[21] = bf2v[0];
        }
    }
    __syncthreads();

    // --- EA/EB (per-side max-subtracted; exact for factorized softmax) ---
    if (live) {
        float A0 = fmaf(s_coef[0], sxi, s_coef[3]);
        float A1 = fmaf(s_coef[1], sxi, s_coef[4]);
        float A2 = fmaf(s_coef[2], sxi, s_coef[5]);
        float mA = fmaxf(A0, fmaxf(A1, A2));
        g_EA[tid] = make_float4(__expf(A0 - mA), __expf(A1 - mA), __expf(A2 - mA), 0.f);
        float B0 = fmaf(s_coef[6], sxi, s_coef[9]);
        float B1 = fmaf(s_coef[7], sxi, s_coef[10]);
        float B2 = fmaf(s_coef[8], sxi, s_coef[11]);
        float mB = fmaxf(B0, fmaxf(B1, B2));
        g_EB[tid] = make_float4(__expf(B0 - mB), __expf(B1 - mB), __expf(B2 - mB), 0.f);
    } else {
        g_EA[tid] = make_float4(0.f, 0.f, 0.f, 0.f);
        g_EB[tid] = make_float4(0.f, 0.f, 0.f, 1.f);  // pad: d += 1, w = 0
    }
}

// ---------------------------------------------------------------------------
// Kernel 2: one block (128 threads = 4 warps) per row i; each thread does 8
// j's. Packed f32x2 FMAs in the loop; distributed binary-exchange butterfly
// (31 SHFL) for the 27-way reduction; tiny smem stage for the cross-warp sum.
// ---------------------------------------------------------------------------
__global__ void __launch_bounds__(128, 5) k_main(float* __restrict__ out)
{
    const int i    = blockIdx.x;
    const int tid  = threadIdx.x;
    const int lane = tid & 31;
    const int warp = tid >> 5;
    const float4 ea = g_EA[i];

    float2 accU[12];                 // [k*4 + bp], pairs (b=2bp, 2bp+1)
    #pragma unroll
    for (int q = 0; q < 12; q++) accU[q] = make_float2(0.f, 0.f);
    float t0 = 0.f, t1 = 0.f, t2 = 0.f;

    #pragma unroll 4
    for (int u = 0; u < 8; u++) {
        const int j = u * 128 + tid;
        float4 eb = g_EB[j];
        float4 xa = g_xt[2 * j];
        float4 xb = g_xt[2 * j + 1];
        // pad rows: eb=(0,0,0,1) -> d=1, w=0, x=0 -> zero contribution
        float d = fmaf(ea.x, eb.x, fmaf(ea.y, eb.y, fmaf(ea.z, eb.z, eb.w)));
        float r = __fdividef(1.f, d);
        float w0 = eb.x * r, w1 = eb.y * r, w2 = eb.z * r;
        t0 += w0; t1 += w1; t2 += w2;
        float2 xp[4] = { make_float2(xa.x, xa.y), make_float2(xa.z, xa.w),
                         make_float2(xb.x, xb.y), make_float2(xb.z, xb.w) };
        float2 wp0 = make_float2(w0, w0);
        float2 wp1 = make_float2(w1, w1);
        float2 wp2 = make_float2(w2, w2);
        #pragma unroll
        for (int bp = 0; bp < 4; bp++) {
            ffma2(accU[0 * 4 + bp], wp0, xp[bp]);
            ffma2(accU[1 * 4 + bp], wp1, xp[bp]);
            ffma2(accU[2 * 4 + bp], wp2, xp[bp]);
        }
    }

    // expand to 32 slots: v[0..2]=T, v[3 + b*3 + k]=U[b,k], v[27..31]=0
    float v[32];
    v[0] = t0; v[1] = t1; v[2] = t2;
    #pragma unroll
    for (int bp = 0; bp < 4; bp++)
        #pragma unroll
        for (int k = 0; k < 3; k++) {
            v[3 + (2 * bp) * 3 + k]     = accU[k * 4 + bp].x;
            v[3 + (2 * bp + 1) * 3 + k] = accU[k * 4 + bp].y;
        }
    #pragma unroll
    for (int s = 27; s < 32; s++) v[s] = 0.f;

    // distributed binary-exchange reduce: lane l ends with total of slot bitrev5(l)
    #pragma unroll
    for (int lev = 0; lev < 5; lev++) {
        const int d = 1 << lev;
        const int half = 16 >> lev;
        const bool up = (lane & d) != 0;
        #pragma unroll
        for (int s = 0; s < half; s++) {
            float keep = up ? v[s + half] : v[s];
            float send = up ? v[s] : v[s + half];
            float recv = __shfl_xor_sync(0xffffffffu, send, d);
            v[s] = keep + recv;
        }
    }
    const int br = ((lane & 1) << 4) | ((lane & 2) << 2) | (lane & 4)
                 | ((lane & 8) >> 2) | ((lane & 16) >> 4);

    __shared__ float s_v[4][32];
    s_v[warp][br] = v[0];
    __syncthreads();

    if (tid < 8) {
        const int b = tid;
        float eav[3] = {ea.x, ea.y, ea.z};
        float xbi = ((const float*)&g_xt[2 * i])[b];
        float ve0 = 0.f, ve1 = 0.f;
        #pragma unroll
        for (int k = 0; k < 3; k++) {
            float T = ((s_v[0][k] + s_v[1][k]) + (s_v[2][k] + s_v[3][k]));
            int s = 3 + b * 3 + k;
            float U = ((s_v[0][s] + s_v[1][s]) + (s_v[2][s] + s_v[3][s]));
            float Tk = eav[k] * T;
            float Uk = eav[k] * U;
            ve0 += fmaf(xbi, g_cc[(k * 2 + 0) * 3 + 1], g_cc[(k * 2 + 0) * 3 + 0]) * Tk
                 + g_cc[(k * 2 + 0) * 3 + 2] * Uk;
            ve1 += fmaf(xbi, g_cc[(k * 2 + 1) * 3 + 1], g_cc[(k * 2 + 1) * 3 + 0]) * Tk
                 + g_cc[(k * 2 + 1) * 3 + 2] * Uk;
        }
        out[b * Nn + i] = xbi * (1.f + g_cc[20]) + g_cc[21]
                        + ve0 * g_cc[18] + ve1 * g_cc[19];
    }
}

extern "C" void kernel_launch(void* const* d_in, const int* in_sizes, int n_in,
                              void* d_out, int out_size)
{
    (void)in_sizes; (void)n_in; (void)out_size;
    k_pre<<<1, 1024>>>(
        (const float*)d_in[0],
        (const float*)d_in[1],  (const float*)d_in[2],
        (const float*)d_in[3],  (const float*)d_in[4],
        (const float*)d_in[5],  (const float*)d_in[6],
        (const float*)d_in[7],  (const float*)d_in[8],
        (const float*)d_in[9],  (const float*)d_in[10],
        (const float*)d_in[11], (const float*)d_in[12],
        (const float*)d_in[13], (const float*)d_in[14]);
    k_main<<<Nn, 128>>>((float*)d_out);
}

// round 5
// speedup vs baseline: 1.2786x; 1.0151x over previous
#include <cuda_runtime.h>

#define Nn   1000
#define NP   1024      // padded
#define Bb   8

// Scratch (static __device__ — no allocation). Padded to NP.
__device__ float4 g_EA[NP];
__device__ float4 g_EB[NP];       // pad rows = (0,0,0,1) -> d contribution 1, w = 0
__device__ float4 g_xt[2 * NP];   // xt[i] = x[0..7][i] transposed; pad rows = 0
__device__ float  g_cc[32];       // c0/c1/c2 [k][m] (18) + Wf2v (3) + bf2v (1)

// ---- packed f32x2 helpers (Blackwell) ----
__device__ __forceinline__ void ffma2(float2& d, const float2 a, const float2 b) {
    asm("fma.rn.f32x2 %0, %1, %2, %0;"
        : "+l"(reinterpret_cast<unsigned long long&>(d))
        : "l"(reinterpret_cast<const unsigned long long&>(a)),
          "l"(reinterpret_cast<const unsigned long long&>(b)));
}

// ---------------------------------------------------------------------------
// Kernel 1: single block, 1024 threads. Thread t owns row i=t. Coefficients
// computed on warp 0 only and broadcast via smem.
// ---------------------------------------------------------------------------
__global__ void __launch_bounds__(1024) k_pre(
    const float* __restrict__ x,
    const float* __restrict__ W1,   const float* __restrict__ b1,
    const float* __restrict__ W2,   const float* __restrict__ b2,
    const float* __restrict__ Wf1e, const float* __restrict__ bf1e,
    const float* __restrict__ Wf2e, const float* __restrict__ bf2e,
    const float* __restrict__ Wfk,  const float* __restrict__ bfk,
    const float* __restrict__ Wf1v, const float* __restrict__ bf1v,
    const float* __restrict__ Wf2v, const float* __restrict__ bf2v)
{
    __shared__ float s_red[32];
    __shared__ float s_coef[12];   // aA[3], cA[3], aB[3], cB[3]
    const int tid = threadIdx.x;
    const bool live = (tid < Nn);

    // --- load & transpose my row; sx in register ---
    float v[8];
    float sxi = 0.f;
    #pragma unroll
    for (int b = 0; b < 8; b++) {
        v[b] = live ? x[b * Nn + tid] : 0.f;
        sxi += v[b];
    }
    g_xt[2 * tid]     = make_float4(v[0], v[1], v[2], v[3]);
    g_xt[2 * tid + 1] = make_float4(v[4], v[5], v[6], v[7]);

    // --- global sum X ---
    float px = sxi;
    #pragma unroll
    for (int off = 16; off > 0; off >>= 1)
        px += __shfl_xor_sync(0xffffffffu, px, off);
    if ((tid & 31) == 0) s_red[tid >> 5] = px;
    __syncthreads();

    if (tid < 32) {
        float t = s_red[tid];
        #pragma unroll
        for (int off = 16; off > 0; off >>= 1)
            t += __shfl_xor_sync(0xffffffffu, t, off);
        const float X = t;

        // --- scalar coefficients (warp 0 only) ---
        float alpha[2], beta[2], gamma[2];
        #pragma unroll
        for (int f = 0; f < 2; f++) {
            float sa = 0.f, sb = 0.f, sg = 0.f;
            #pragma unroll
            for (int e = 0; e < 4; e++) {
                float we = Wf1e[(2 * e) * 2 + f];
                float wo = Wf1e[(2 * e + 1) * 2 + f];
                sa += W1[e] * we;
                sb += W1[e] * wo;
                sg += b1[e] * (we + wo);
            }
            alpha[f] = (float)Nn * sa;
            beta[f]  = sb;
            gamma[f] = (float)Nn * (sg + bf1e[f]);
        }
        float ap[3], cv[3];
        #pragma unroll
        for (int vv = 0; vv < 3; vv++) {
            float a = 0.f, bq = 0.f, g = 0.f;
            #pragma unroll
            for (int f = 0; f < 2; f++) {
                float w = Wf1v[f * 3 + vv];
                a  += alpha[f] * w;
                bq += beta[f]  * w;
                g  += gamma[f] * w;
            }
            g += bf1v[vv];
            ap[vv] = a;
            cv[vv] = bq * X + (float)Bb * g;
        }
        #pragma unroll
        for (int k = 0; k < 3; k++) {
            float s1 = 0.f, s2 = 0.f, s3 = 0.f, s4 = 0.f;
            #pragma unroll
            for (int vv = 0; vv < 3; vv++) {
                float we = Wf2e[(2 * vv) * 3 + k];
                float wo = Wf2e[(2 * vv + 1) * 3 + k];
                s1 += ap[vv] * we;  s2 += cv[vv] * we;
                s3 += ap[vv] * wo;  s4 += cv[vv] * wo;
            }
            if (tid == 0) {
                s_coef[k]     = s1;            // aA
                s_coef[3 + k] = s2 + bf2e[k];  // cA
                s_coef[6 + k] = s3;            // aB
                s_coef[9 + k] = s4;            // cB
            }
        }

        // --- message-combine constants (lane 0) ---
        if (tid == 0) {
            #pragma unroll
            for (int k = 0; k < 3; k++)
                #pragma unroll
                for (int m = 0; m < 2; m++) {
                    float u1 = 0.f, v1 = 0.f, u2 = 0.f, v2 = 0.f;
                    #pragma unroll
                    for (int e = 0; e < 4; e++) {
                        float we = Wfk[k * 16 + (2 * e) * 2 + m];
                        float wo = Wfk[k * 16 + (2 * e + 1) * 2 + m];
                        u1 += W2[e] * we;  v1 += b2[e] * we;
                        u2 += W2[e] * wo;  v2 += b2[e] * wo;
                    }
                    int km = k * 2 + m;
                    g_cc[km * 3 + 0] = v1 + v2 + bfk[km];
                    g_cc[km * 3 + 1] = u1;
                    g_cc[km * 3 + 2] = u2;
                }
            g_cc[18] = Wf2v[0]; g_cc[19] = Wf2v[1];
            g_cc[20] = Wf2v[2]; g_cc[21] = bf2v[0];
        }
    }
    __syncthreads();

    // --- EA/EB (per-side max-subtracted; exact for factorized softmax) ---
    if (live) {
        float A0 = fmaf(s_coef[0], sxi, s_coef[3]);
        float A1 = fmaf(s_coef[1], sxi, s_coef[4]);
        float A2 = fmaf(s_coef[2], sxi, s_coef[5]);
        float mA = fmaxf(A0, fmaxf(A1, A2));
        g_EA[tid] = make_float4(__expf(A0 - mA), __expf(A1 - mA), __expf(A2 - mA), 0.f);
        float B0 = fmaf(s_coef[6], sxi, s_coef[9]);
        float B1 = fmaf(s_coef[7], sxi, s_coef[10]);
        float B2 = fmaf(s_coef[8], sxi, s_coef[11]);
        float mB = fmaxf(B0, fmaxf(B1, B2));
        g_EB[tid] = make_float4(__expf(B0 - mB), __expf(B1 - mB), __expf(B2 - mB), 0.f);
    } else {
        g_EA[tid] = make_float4(0.f, 0.f, 0.f, 0.f);
        g_EB[tid] = make_float4(0.f, 0.f, 0.f, 1.f);  // pad: d += 1, w = 0
    }
}

// ---------------------------------------------------------------------------
// Kernel 2: one block (128 threads) per row i; each thread does 8 j's in two
// Montgomery batches of 4 (1 MUFU.RCP per 4 pairs; d in (1,4] so products
// are in (1,256] — no range risk). Packed f32x2 FMAs for the 24 U-MACs.
// Distributed binary-exchange butterfly for the 27-way reduction.
// ---------------------------------------------------------------------------
__global__ void __launch_bounds__(128, 4) k_main(float* __restrict__ out)
{
    const int i    = blockIdx.x;
    const int tid  = threadIdx.x;
    const int lane = tid & 31;
    const int warp = tid >> 5;
    const float4 ea = g_EA[i];

    float2 accU[12];                 // [k*4 + bp], pairs (b=2bp, 2bp+1)
    #pragma unroll
    for (int q = 0; q < 12; q++) accU[q] = make_float2(0.f, 0.f);
    float t0 = 0.f, t1 = 0.f, t2 = 0.f;

    #pragma unroll
    for (int half = 0; half < 2; half++) {
        float4 eb[4], xa[4], xb[4];
        #pragma unroll
        for (int t = 0; t < 4; t++) {
            const int j = (half * 4 + t) * 128 + tid;
            eb[t] = g_EB[j];
            xa[t] = g_xt[2 * j];
            xb[t] = g_xt[2 * j + 1];
        }
        // denominators (pad rows: eb=(0,0,0,1) -> d=1, w=0, x=0 -> no contrib)
        float d0 = fmaf(ea.x, eb[0].x, fmaf(ea.y, eb[0].y, fmaf(ea.z, eb[0].z, eb[0].w)));
        float d1 = fmaf(ea.x, eb[1].x, fmaf(ea.y, eb[1].y, fmaf(ea.z, eb[1].z, eb[1].w)));
        float d2 = fmaf(ea.x, eb[2].x, fmaf(ea.y, eb[2].y, fmaf(ea.z, eb[2].z, eb[2].w)));
        float d3 = fmaf(ea.x, eb[3].x, fmaf(ea.y, eb[3].y, fmaf(ea.z, eb[3].z, eb[3].w)));
        // batch inversion: one reciprocal for four denominators
        float p1 = d0 * d1;
        float p2 = p1 * d2;
        float p3 = p2 * d3;
        float r  = __fdividef(1.f, p3);
        float inv[4];
        inv[3]   = r * p2;
        float r2 = r * d3;
        inv[2]   = r2 * p1;
        float r1 = r2 * d2;
        inv[1]   = r1 * d0;
        inv[0]   = r1 * d1;

        #pragma unroll
        for (int t = 0; t < 4; t++) {
            float w0 = eb[t].x * inv[t];
            float w1 = eb[t].y * inv[t];
            float w2 = eb[t].z * inv[t];
            t0 += w0; t1 += w1; t2 += w2;
            float2 xp[4] = { make_float2(xa[t].x, xa[t].y), make_float2(xa[t].z, xa[t].w),
                             make_float2(xb[t].x, xb[t].y), make_float2(xb[t].z, xb[t].w) };
            float2 wp0 = make_float2(w0, w0);
            float2 wp1 = make_float2(w1, w1);
            float2 wp2 = make_float2(w2, w2);
            #pragma unroll
            for (int bp = 0; bp < 4; bp++) {
                ffma2(accU[0 * 4 + bp], wp0, xp[bp]);
                ffma2(accU[1 * 4 + bp], wp1, xp[bp]);
                ffma2(accU[2 * 4 + bp], wp2, xp[bp]);
            }
        }
    }

    // expand to 32 slots: v[0..2]=T, v[3 + b*3 + k]=U[b,k], v[27..31]=0
    float v[32];
    v[0] = t0; v[1] = t1; v[2] = t2;
    #pragma unroll
    for (int bp = 0; bp < 4; bp++)
        #pragma unroll
        for (int k = 0; k < 3; k++) {
            v[3 + (2 * bp) * 3 + k]     = accU[k * 4 + bp].x;
            v[3 + (2 * bp + 1) * 3 + k] = accU[k * 4 + bp].y;
        }
    #pragma unroll
    for (int s = 27; s < 32; s++) v[s] = 0.f;

    // distributed binary-exchange reduce: lane l ends with total of slot bitrev5(l)
    #pragma unroll
    for (int lev = 0; lev < 5; lev++) {
        const int d = 1 << lev;
        const int half = 16 >> lev;
        const bool up = (lane & d) != 0;
        #pragma unroll
        for (int s = 0; s < half; s++) {
            float keep = up ? v[s + half] : v[s];
            float send = up ? v[s] : v[s + half];
            float recv = __shfl_xor_sync(0xffffffffu, send, d);
            v[s] = keep + recv;
        }
    }
    const int br = ((lane & 1) << 4) | ((lane & 2) << 2) | (lane & 4)
                 | ((lane & 8) >> 2) | ((lane & 16) >> 4);

    __shared__ float s_v[4][32];
    s_v[warp][br] = v[0];
    __syncthreads();

    if (tid < 8) {
        const int b = tid;
        float eav[3] = {ea.x, ea.y, ea.z};
        float xbi = ((const float*)&g_xt[2 * i])[b];
        float ve0 = 0.f, ve1 = 0.f;
        #pragma unroll
        for (int k = 0; k < 3; k++) {
            float T = ((s_v[0][k] + s_v[1][k]) + (s_v[2][k] + s_v[3][k]));
            int s = 3 + b * 3 + k;
            float U = ((s_v[0][s] + s_v[1][s]) + (s_v[2][s] + s_v[3][s]));
            float Tk = eav[k] * T;
            float Uk = eav[k] * U;
            ve0 += fmaf(xbi, g_cc[(k * 2 + 0) * 3 + 1], g_cc[(k * 2 + 0) * 3 + 0]) * Tk
                 + g_cc[(k * 2 + 0) * 3 + 2] * Uk;
            ve1 += fmaf(xbi, g_cc[(k * 2 + 1) * 3 + 1], g_cc[(k * 2 + 1) * 3 + 0]) * Tk
                 + g_cc[(k * 2 + 1) * 3 + 2] * Uk;
        }
        out[b * Nn + i] = xbi * (1.f + g_cc[20]) + g_cc[21]
                        + ve0 * g_cc[18] + ve1 * g_cc[19];
    }
}

extern "C" void kernel_launch(void* const* d_in, const int* in_sizes, int n_in,
                              void* d_out, int out_size)
{
    (void)in_sizes; (void)n_in; (void)out_size;
    k_pre<<<1, 1024>>>(
        (const float*)d_in[0],
        (const float*)d_in[1],  (const float*)d_in[2],
        (const float*)d_in[3],  (const float*)d_in[4],
        (const float*)d_in[5],  (const float*)d_in[6],
        (const float*)d_in[7],  (const float*)d_in[8],
        (const float*)d_in[9],  (const float*)d_in[10],
        (const float*)d_in[11], (const float*)d_in[12],
        (const float*)d_in[13], (const float*)d_in[14]);
    k_main<<<Nn, 128>>>((float*)d_out);
}